// round 16
// baseline (speedup 1.0000x reference)
#include <cuda_runtime.h>
#include <cuda_fp16.h>

// GaussianWarpingScheme on GB300 — round 16.
// Producer (LTS-capped, has issue headroom): transpose im -> fp16 HWC scratch
//   AND precompute per-pixel params: float4 fused tap weights (f32) + int2
//   packed row-base offsets ((y<<8)+xb).
// Main (r9 body, param math removed): per lane load params (4 coalesced
//   LDGs), 8 up-front gather LDG.128 (MLP=8), FFMA2 accumulate, direct stores.

#define Bn 8
#define Cn 16
#define Hn 256
#define Wn 256
#define HWn (Hn * Wn)
#define NPIX (Bn * HWn)

__device__ __half  g_imH[(size_t)NPIX * Cn];   // 32 MB channel-last scratch
__device__ float4  g_wt[NPIX];                 // fused tap weights (w00,w01,w10,w11)
__device__ int2    g_ix[NPIX];                 // packed ((y0<<8)+xb, (y1<<8)+xb)

// ---- packed f32x2 helpers ----
__device__ __forceinline__ unsigned long long f2pack(float lo, float hi) {
    unsigned long long r;
    asm("mov.b64 %0,{%1,%2};" : "=l"(r) : "f"(lo), "f"(hi));
    return r;
}
__device__ __forceinline__ unsigned long long h2f2(unsigned int h2) {
    const float2 f = __half22float2(*(const __half2*)&h2);
    return f2pack(f.x, f.y);
}
__device__ __forceinline__ unsigned long long fma2(unsigned long long a,
                                                   unsigned long long b,
                                                   unsigned long long c) {
    unsigned long long d;
    asm("fma.rn.f32x2 %0,%1,%2,%3;" : "=l"(d) : "l"(a), "l"(b), "l"(c));
    return d;
}
__device__ __forceinline__ unsigned long long mul2(unsigned long long a,
                                                   unsigned long long b) {
    unsigned long long d;
    asm("mul.rn.f32x2 %0,%1,%2;" : "=l"(d) : "l"(a), "l"(b));
    return d;
}
__device__ __forceinline__ float2 f2unpack(unsigned long long a) {
    float2 f;
    asm("mov.b64 {%0,%1},%2;" : "=f"(f.x), "=f"(f.y) : "l"(a));
    return f;
}

// ------------- Producer: transpose + per-pixel params -------------
__global__ void __launch_bounds__(256)
producer_pass(const float* __restrict__ im,
              const float* __restrict__ w)
{
    const int bh = blockIdx.x;          // 0 .. B*H-1
    const int b  = bh >> 8;
    const int h  = bh & (Hn - 1);
    const int wv = threadIdx.x;         // x coordinate

    // ---- transpose 16 channels of this pixel ----
    const float* src = im + ((size_t)(b * Cn) * Hn + h) * Wn + wv;
    __half* dst = g_imH + ((size_t)((b << 8) + h) * Wn + wv) * Cn;

    __half hv[Cn];
#pragma unroll
    for (int c = 0; c < Cn; c++)
        hv[c] = __float2half_rn(src[(size_t)c * HWn]);

    *(uint4*)(dst)     = *(const uint4*)(hv);
    *(uint4*)(dst + 8) = *(const uint4*)(hv + 8);

    // ---- per-pixel params (coalesced w loads / param stores) ----
    const int rem = (h << 8) + wv;
    const int gp  = b * HWn + rem;

    const float w0 = w[b * 2 * HWn + rem];
    const float w1 = w[b * 2 * HWn + HWn + rem];

    const float bx = -1.0f + (float)wv * (2.0f / 255.0f);
    const float by = -1.0f + (float)h  * (2.0f / 255.0f);
    const float x = ((bx - w0) + 1.0f) * 0.5f * 255.0f;
    const float y = ((by - w1) + 1.0f) * 0.5f * 255.0f;
    const int ix = (int)floorf(x);
    const int iy = (int)floorf(y);
    const float fx = x - (float)ix;
    const float fy = y - (float)iy;

    const float wx0m = (ix     >= 0 && ix     < Wn) ? __expf(-8.0f * fx * fx)               : 0.0f;
    const float wx1m = (ix + 1 >= 0 && ix + 1 < Wn) ? __expf(-8.0f * (1.0f-fx) * (1.0f-fx)) : 0.0f;
    const float wy0m = (iy     >= 0 && iy     < Hn) ? __expf(-8.0f * fy * fy)               : 0.0f;
    const float wy1m = (iy + 1 >= 0 && iy + 1 < Hn) ? __expf(-8.0f * (1.0f-fy) * (1.0f-fy)) : 0.0f;

    // x-pair base with boundary-correct slot weights
    const int xb = min(max(ix, 0), Wn - 2);
    float pw0 = 0.0f, pw1 = 0.0f;
    if (ix     == xb)     pw0 += wx0m;
    if (ix + 1 == xb)     pw0 += wx1m;            // ix = -1
    if (ix     == xb + 1) pw1 += wx0m;            // ix = 255
    if (ix + 1 == xb + 1) pw1 += wx1m;

    const int y0 = min(max(iy,     0), Hn - 1);
    const int y1 = min(max(iy + 1, 0), Hn - 1);

    g_wt[gp] = make_float4(pw0 * wy0m, pw1 * wy0m, pw0 * wy1m, pw1 * wy1m);
    g_ix[gp] = make_int2((y0 << 8) + xb, (y1 << 8) + xb);
}

// ------------- Main: gather only (params precomputed) -------------
__global__ void __launch_bounds__(256)
gauss_warp_main(float* __restrict__ out)
{
    const int tid  = threadIdx.x;
    const int q    = tid >> 1;                    // pixel slot 0..127
    const int csel = tid & 1;                     // channel half

    const int pA = blockIdx.x * 256 + q;
    const int pB = pA + 128;
    const int b  = pA >> 16;
    const int rA = pA & (HWn - 1);

    // ---- params: coalesced (2 lanes broadcast-share each value) ----
    const float4 wA = __ldg(&g_wt[pA]);
    const float4 wB = __ldg(&g_wt[pB]);
    const int2   iA = __ldg(&g_ix[pA]);
    const int2   iB = __ldg(&g_ix[pB]);

    const __half* bh = g_imH + (size_t)b * HWn * Cn;
    const int co = csel * 8;
    const __half* a0p = bh + (size_t)iA.x * Cn + co;
    const __half* a1p = bh + (size_t)iA.y * Cn + co;
    const __half* b0p = bh + (size_t)iB.x * Cn + co;
    const __half* b1p = bh + (size_t)iB.y * Cn + co;

    // ---- issue all 8 gathers up front (MLP = 8 per lane) ----
    const uint4 a00 = __ldg((const uint4*)a0p);
    const uint4 a01 = __ldg((const uint4*)a0p + 2);
    const uint4 a10 = __ldg((const uint4*)a1p);
    const uint4 a11 = __ldg((const uint4*)a1p + 2);
    const uint4 b00 = __ldg((const uint4*)b0p);
    const uint4 b01 = __ldg((const uint4*)b0p + 2);
    const uint4 b10 = __ldg((const uint4*)b1p);
    const uint4 b11 = __ldg((const uint4*)b1p + 2);

    const unsigned long long A00 = f2pack(wA.x, wA.x);
    const unsigned long long A01 = f2pack(wA.y, wA.y);
    const unsigned long long A10 = f2pack(wA.z, wA.z);
    const unsigned long long A11 = f2pack(wA.w, wA.w);

    unsigned long long s0, s1, s2, s3;
    s0 = mul2(A00, h2f2(a00.x));
    s1 = mul2(A00, h2f2(a00.y));
    s2 = mul2(A00, h2f2(a00.z));
    s3 = mul2(A00, h2f2(a00.w));
    s0 = fma2(A01, h2f2(a01.x), s0);
    s1 = fma2(A01, h2f2(a01.y), s1);
    s2 = fma2(A01, h2f2(a01.z), s2);
    s3 = fma2(A01, h2f2(a01.w), s3);
    s0 = fma2(A10, h2f2(a10.x), s0);
    s1 = fma2(A10, h2f2(a10.y), s1);
    s2 = fma2(A10, h2f2(a10.z), s2);
    s3 = fma2(A10, h2f2(a10.w), s3);
    s0 = fma2(A11, h2f2(a11.x), s0);
    s1 = fma2(A11, h2f2(a11.y), s1);
    s2 = fma2(A11, h2f2(a11.z), s2);
    s3 = fma2(A11, h2f2(a11.w), s3);

    float* opA = out + (size_t)b * Cn * HWn + (size_t)co * HWn + rA;
    {
        const float2 f0 = f2unpack(s0);
        const float2 f1 = f2unpack(s1);
        const float2 f2 = f2unpack(s2);
        const float2 f3 = f2unpack(s3);
        opA[0 * HWn] = f0.x;  opA[1 * HWn] = f0.y;
        opA[2 * HWn] = f1.x;  opA[3 * HWn] = f1.y;
        opA[4 * HWn] = f2.x;  opA[5 * HWn] = f2.y;
        opA[6 * HWn] = f3.x;  opA[7 * HWn] = f3.y;
    }

    const unsigned long long B00 = f2pack(wB.x, wB.x);
    const unsigned long long B01 = f2pack(wB.y, wB.y);
    const unsigned long long B10 = f2pack(wB.z, wB.z);
    const unsigned long long B11 = f2pack(wB.w, wB.w);

    s0 = mul2(B00, h2f2(b00.x));
    s1 = mul2(B00, h2f2(b00.y));
    s2 = mul2(B00, h2f2(b00.z));
    s3 = mul2(B00, h2f2(b00.w));
    s0 = fma2(B01, h2f2(b01.x), s0);
    s1 = fma2(B01, h2f2(b01.y), s1);
    s2 = fma2(B01, h2f2(b01.z), s2);
    s3 = fma2(B01, h2f2(b01.w), s3);
    s0 = fma2(B10, h2f2(b10.x), s0);
    s1 = fma2(B10, h2f2(b10.y), s1);
    s2 = fma2(B10, h2f2(b10.z), s2);
    s3 = fma2(B10, h2f2(b10.w), s3);
    s0 = fma2(B11, h2f2(b11.x), s0);
    s1 = fma2(B11, h2f2(b11.y), s1);
    s2 = fma2(B11, h2f2(b11.z), s2);
    s3 = fma2(B11, h2f2(b11.w), s3);

    float* opB = opA + 128;           // pB = pA + 128, same row span
    {
        const float2 f0 = f2unpack(s0);
        const float2 f1 = f2unpack(s1);
        const float2 f2 = f2unpack(s2);
        const float2 f3 = f2unpack(s3);
        opB[0 * HWn] = f0.x;  opB[1 * HWn] = f0.y;
        opB[2 * HWn] = f1.x;  opB[3 * HWn] = f1.y;
        opB[4 * HWn] = f2.x;  opB[5 * HWn] = f2.y;
        opB[6 * HWn] = f3.x;  opB[7 * HWn] = f3.y;
    }
}

extern "C" void kernel_launch(void* const* d_in, const int* in_sizes, int n_in,
                              void* d_out, int out_size)
{
    const float* im = (const float*)d_in[0];
    const float* w  = (const float*)d_in[1];
    if (n_in >= 2 && in_sizes[0] == Bn * 2 * HWn && in_sizes[1] == Bn * Cn * HWn) {
        im = (const float*)d_in[1];
        w  = (const float*)d_in[0];
    }
    float* out = (float*)d_out;

    producer_pass<<<Bn * Hn, 256>>>(im, w);
    gauss_warp_main<<<NPIX / 256, 256>>>(out);
}